// round 2
// baseline (speedup 1.0000x reference)
#include <cuda_runtime.h>

// EdgeAugmentation: LayerNorm over a singleton axis makes every score == beta,
// so top_k (stable ties, lower-index-first in XLA CPU & GPU) picks the first
// TOPK row-major (i,j) per graph that are neither an existing same-graph edge
// nor on the diagonal. Output buffer is float32 (concatenated reference tuple).

#define E_EDGES 65536
#define BQ      64
#define NG      128
#define TOPK_K  16
#define AUG     (E_EDGES + BQ * TOPK_K)   // 66560 columns in aug_edge_index
#define WORDS   512                        // 128*128 bits / 32

// Per-graph adjacency-existence bitmap (64 graphs x 16384 bits = 128 KB).
__device__ unsigned int g_exist[BQ][WORDS];

// Copy original edges to output (as float) and set existence bits.
// Vectorized: each thread handles 4 edges.
__global__ void build_kernel(const int* __restrict__ ei, float* __restrict__ out) {
    int t = blockIdx.x * blockDim.x + threadIdx.x;   // 0 .. E/4-1
    if (t >= E_EDGES / 4) return;

    int4 s4 = ((const int4*)ei)[t];
    int4 d4 = ((const int4*)(ei + E_EDGES))[t];

    float4 fs = make_float4((float)s4.x, (float)s4.y, (float)s4.z, (float)s4.w);
    float4 fd = make_float4((float)d4.x, (float)d4.y, (float)d4.z, (float)d4.w);
    ((float4*)out)[t] = fs;                                   // row 0 (src), offset 4t
    // row 1 (dst) at offset AUG + 4t: AUG = 66560 is divisible by 4.
    ((float4*)(out + AUG))[t] = fd;

    int ss[4] = { s4.x, s4.y, s4.z, s4.w };
    int dd[4] = { d4.x, d4.y, d4.z, d4.w };
    #pragma unroll
    for (int k = 0; k < 4; k++) {
        int s = ss[k], d = dd[k];
        int g = s >> 7;                          // src // Ng
        if ((d >> 7) == g) {                     // same-graph edge only
            int bit = ((s & 127) << 7) | (d & 127);   // sl*Ng + dl
            atomicOr(&g_exist[g][bit >> 5], 1u << (bit & 31));
        }
    }
}

// One block per graph: rank-scan the free-bitmap, emit first TOPK free (i,j).
__global__ void topk_kernel(float* __restrict__ out, int write_count) {
    int b    = blockIdx.x;
    int w    = threadIdx.x;      // word index 0..511
    int lane = w & 31;
    int wid  = w >> 5;

    unsigned m = ~g_exist[b][w];         // free = not existing
    // Clear the (at most one) diagonal bit in this word: positions p = 129*i.
    int lo = w << 5;
    int i0 = (lo + 128) / 129;
    int p  = i0 * 129;
    if (p < lo + 32) m &= ~(1u << (p - lo));

    int c = __popc(m);

    // Inclusive warp scan of popcounts.
    int v = c;
    #pragma unroll
    for (int off = 1; off < 32; off <<= 1) {
        int t = __shfl_up_sync(0xffffffffu, v, off);
        if (lane >= off) v += t;
    }
    __shared__ int wsum[16];
    if (lane == 31) wsum[wid] = v;
    __syncthreads();
    // Scan the 16 warp totals in warp 0.
    if (wid == 0) {
        int x = (lane < 16) ? wsum[lane] : 0;
        #pragma unroll
        for (int off = 1; off < 16; off <<= 1) {
            int t = __shfl_up_sync(0xffffffffu, x, off);
            if (lane >= off) x += t;
        }
        if (lane < 16) wsum[lane] = x;
    }
    __syncthreads();

    int excl = v - c + (wid > 0 ? wsum[wid - 1] : 0);  // global exclusive rank

    if (excl < TOPK_K && m) {
        unsigned mm = m;
        int r    = excl;
        int boff = b << 7;  // b * Ng
        while (mm && r < TOPK_K) {
            int bi = __ffs(mm) - 1;
            mm &= mm - 1;
            int bitpos = lo + bi;
            out[E_EDGES + b * TOPK_K + r]       = (float)(boff + (bitpos >> 7));  // new_src
            out[AUG + E_EDGES + b * TOPK_K + r] = (float)(boff + (bitpos & 127)); // new_dst
            r++;
        }
    }

    if (b == 0 && w == 0 && write_count) out[2 * AUG] = (float)(BQ * TOPK_K);  // added_count
}

extern "C" void kernel_launch(void* const* d_in, const int* in_sizes, int n_in,
                              void* d_out, int out_size) {
    // Locate edge_index by its unique element count (2 * E = 131072, int32).
    const int* ei = nullptr;
    for (int i = 0; i < n_in; i++) {
        if (in_sizes[i] == 2 * E_EDGES) { ei = (const int*)d_in[i]; break; }
    }
    float* out = (float*)d_out;

    // Zero the existence bitmap (capturable memset node; no allocations).
    void* pexist = nullptr;
    cudaGetSymbolAddress(&pexist, g_exist);
    cudaMemsetAsync(pexist, 0, sizeof(unsigned int) * BQ * WORDS);

    build_kernel<<<E_EDGES / 4 / 256, 256>>>(ei, out);
    topk_kernel<<<BQ, WORDS>>>(out, (out_size > 2 * AUG) ? 1 : 0);
}